// round 8
// baseline (speedup 1.0000x reference)
#include <cuda_runtime.h>
#include <cuda_bf16.h>
#include <cuda_fp16.h>
#include <cstdint>

#define BATCH 8
#define NN    2048
#define KDIM  256
#define DOUT  64
#define ALPHA 0.2f

// ---------------- scratch ----------------
__device__ __half g_WhT[BATCH * DOUT * NN];   // [b][d][j] fp16, 2MB
__device__ float g_s1[BATCH * NN];
__device__ float g_s2[BATCH * NN];
__device__ unsigned int g_s2max_u[BATCH];     // order-preserving float keys

// ---------------- helpers ----------------
__device__ __forceinline__ uint32_t smem_u32(const void* p) {
    uint32_t a;
    asm("{ .reg .u64 t; cvta.to.shared.u64 t, %1; cvt.u32.u64 %0, t; }" : "=r"(a) : "l"(p));
    return a;
}
__device__ __forceinline__ void ldsm4(uint32_t (&r)[4], uint32_t addr) {
    asm volatile("ldmatrix.sync.aligned.m8n8.x4.shared.b16 {%0,%1,%2,%3}, [%4];"
                 : "=r"(r[0]), "=r"(r[1]), "=r"(r[2]), "=r"(r[3]) : "r"(addr));
}
__device__ __forceinline__ void mma_bf16(float (&d)[4], const uint32_t (&a)[4],
                                         uint32_t b0, uint32_t b1) {
    asm volatile("mma.sync.aligned.m16n8k16.row.col.f32.bf16.bf16.f32 "
                 "{%0,%1,%2,%3}, {%4,%5,%6,%7}, {%8,%9}, {%0,%1,%2,%3};"
                 : "+f"(d[0]), "+f"(d[1]), "+f"(d[2]), "+f"(d[3])
                 : "r"(a[0]), "r"(a[1]), "r"(a[2]), "r"(a[3]), "r"(b0), "r"(b1));
}
__device__ __forceinline__ void mma_f16(float (&d)[4], const uint32_t (&a)[4],
                                        uint32_t b0, uint32_t b1) {
    asm volatile("mma.sync.aligned.m16n8k16.row.col.f32.f16.f16.f32 "
                 "{%0,%1,%2,%3}, {%4,%5,%6,%7}, {%8,%9}, {%0,%1,%2,%3};"
                 : "+f"(d[0]), "+f"(d[1]), "+f"(d[2]), "+f"(d[3])
                 : "r"(a[0]), "r"(a[1]), "r"(a[2]), "r"(a[3]), "r"(b0), "r"(b1));
}
__device__ __forceinline__ uint32_t pkbf2(float x, float y) {
    __nv_bfloat162 t = __floats2bfloat162_rn(x, y);
    return *reinterpret_cast<uint32_t*>(&t);
}
__device__ __forceinline__ uint32_t hibits2(float x, float y) {
    return __byte_perm(__float_as_uint(x), __float_as_uint(y), 0x7632);
}
__device__ __forceinline__ float resid(float x) {
    return x - __uint_as_float(__float_as_uint(x) & 0xFFFF0000u);
}
__device__ __forceinline__ uint32_t pkhf2(float x, float y) {
    __half2 t = __floats2half2_rn(x, y);
    return *reinterpret_cast<uint32_t*>(&t);
}
__device__ __forceinline__ uint32_t fkey(float f) {
    const uint32_t b = __float_as_uint(f);
    return b ^ ((uint32_t)((int)b >> 31) | 0x80000000u);
}
__device__ __forceinline__ float funkey(uint32_t k) {
    const uint32_t b = (k & 0x80000000u) ? (k ^ 0x80000000u) : ~k;
    return __uint_as_float(b);
}
#define CP_ASYNC16(dst, src) \
    asm volatile("cp.async.cg.shared.global [%0], [%1], 16;" :: "r"(dst), "l"(src) : "memory")
#define CP_COMMIT() asm volatile("cp.async.commit_group;" ::: "memory")
#define CP_WAIT1()  asm volatile("cp.async.wait_group 1;" ::: "memory")

// ============================================================
// Kernel A (HMMA): Wh = h @ W. 256 CTAs x 64 rows, 8 warps, 2 CTAs/SM.
// Emits s1, s2 (+atomicMax key), WhT fp16. 3-split bf16 MMA.  (unchanged)
// ============================================================
#define WOFF_HH 0
#define WOFF_HL 8192
#define WOFF_WH 16384
#define WOFF_WL 24576
#define WOFF_TR 0
#define WOFF_PS 32768
#define WH_SMEM 33792

__global__ __launch_bounds__(256, 2) void wh_kernel(const float* __restrict__ h,
                                                    const float* __restrict__ W,
                                                    const float* __restrict__ a) {
    extern __shared__ char sw[];
    const uint32_t smb = smem_u32(sw);
    const int tid = threadIdx.x;
    const int wid = tid >> 5, lid = tid & 31;
    const int gi0 = blockIdx.x * 64;
    const int b = gi0 >> 11;
    const int rowb = gi0 & 2047;

    float acc[4][4];
    #pragma unroll
    for (int n = 0; n < 4; n++)
        #pragma unroll
        for (int k = 0; k < 4; k++) acc[n][k] = 0.f;

    const int mq = wid & 3, nh = wid >> 2;
    const int rr = lid & 7, q = lid >> 3, qh = q >> 1, ql = q & 1;
    const int rowA = mq * 16 + rr + (ql << 3);
    const uint32_t baseA = (uint32_t)(rowA * 128);
    const int xA = rowA & 7;
    const int rbB = nh * 32 + (qh << 3) + rr;

    const int hrow = tid >> 2, hq = tid & 3;
    const float* hsrc = h + (size_t)(gi0 + hrow) * KDIM + hq * 16;
    const int wdd = tid >> 2, wkg = tid & 3;

    for (int kt = 0; kt < 4; kt++) {
        __syncthreads();
        #pragma unroll
        for (int g = 0; g < 2; g++) {
            const float4 f0 = *reinterpret_cast<const float4*>(hsrc + kt * 64 + g * 8);
            const float4 f1 = *reinterpret_cast<const float4*>(hsrc + kt * 64 + g * 8 + 4);
            uint4 hi4, lo4;
            hi4.x = hibits2(f0.x, f0.y); hi4.y = hibits2(f0.z, f0.w);
            hi4.z = hibits2(f1.x, f1.y); hi4.w = hibits2(f1.z, f1.w);
            lo4.x = pkbf2(resid(f0.x), resid(f0.y));
            lo4.y = pkbf2(resid(f0.z), resid(f0.w));
            lo4.z = pkbf2(resid(f1.x), resid(f1.y));
            lo4.w = pkbf2(resid(f1.z), resid(f1.w));
            const int gran = hq * 2 + g;
            const uint32_t addr = (uint32_t)(hrow * 128 + ((gran ^ (hrow & 7)) << 4));
            *reinterpret_cast<uint4*>(sw + WOFF_HH + addr) = hi4;
            *reinterpret_cast<uint4*>(sw + WOFF_HL + addr) = lo4;
        }
        {
            uint32_t hi[8], lo[8];
            #pragma unroll
            for (int t = 0; t < 8; t++) {
                const float x0 = W[(kt * 64 + wkg * 16 + 2 * t) * DOUT + wdd];
                const float x1 = W[(kt * 64 + wkg * 16 + 2 * t + 1) * DOUT + wdd];
                hi[t] = hibits2(x0, x1);
                lo[t] = pkbf2(resid(x0), resid(x1));
            }
            const uint32_t a0 = (uint32_t)(wdd * 128 + (((wkg * 2) ^ (wdd & 7)) << 4));
            const uint32_t a1 = (uint32_t)(wdd * 128 + (((wkg * 2 + 1) ^ (wdd & 7)) << 4));
            *reinterpret_cast<uint4*>(sw + WOFF_WH + a0) = make_uint4(hi[0], hi[1], hi[2], hi[3]);
            *reinterpret_cast<uint4*>(sw + WOFF_WH + a1) = make_uint4(hi[4], hi[5], hi[6], hi[7]);
            *reinterpret_cast<uint4*>(sw + WOFF_WL + a0) = make_uint4(lo[0], lo[1], lo[2], lo[3]);
            *reinterpret_cast<uint4*>(sw + WOFF_WL + a1) = make_uint4(lo[4], lo[5], lo[6], lo[7]);
        }
        __syncthreads();
        #pragma unroll
        for (int t = 0; t < 4; t++) {
            uint32_t Ah[4], Al[4];
            const uint32_t ua = baseA + (uint32_t)(((2 * t + qh) ^ xA) << 4);
            ldsm4(Ah, smb + WOFF_HH + ua);
            ldsm4(Al, smb + WOFF_HL + ua);
            #pragma unroll
            for (int ntp = 0; ntp < 2; ntp++) {
                const int rowB = rbB + ntp * 16;
                const uint32_t ab = (uint32_t)(rowB * 128 + (((2 * t + ql) ^ (rowB & 7)) << 4));
                uint32_t Bh[4], Bl[4];
                ldsm4(Bh, smb + WOFF_WH + ab);
                ldsm4(Bl, smb + WOFF_WL + ab);
                mma_bf16(acc[2 * ntp],     Ah, Bh[0], Bh[1]);
                mma_bf16(acc[2 * ntp],     Ah, Bl[0], Bl[1]);
                mma_bf16(acc[2 * ntp],     Al, Bh[0], Bh[1]);
                mma_bf16(acc[2 * ntp + 1], Ah, Bh[2], Bh[3]);
                mma_bf16(acc[2 * ntp + 1], Ah, Bl[2], Bl[3]);
                mma_bf16(acc[2 * ntp + 1], Al, Bh[2], Bh[3]);
            }
        }
    }
    __syncthreads();

    const int r0 = mq * 16 + (lid >> 2), r1 = r0 + 8;
    float s1r0 = 0.f, s2r0 = 0.f, s1r1 = 0.f, s2r1 = 0.f;
    __half* tr = reinterpret_cast<__half*>(sw + WOFF_TR);
    float* ps1 = reinterpret_cast<float*>(sw + WOFF_PS);
    float* ps2 = ps1 + 128;
    #pragma unroll
    for (int nt = 0; nt < 4; nt++) {
        const int d0 = nh * 32 + nt * 8 + (lid & 3) * 2;
        const float a10 = a[d0], a11 = a[d0 + 1];
        const float a20 = a[64 + d0], a21 = a[64 + d0 + 1];
        s1r0 = fmaf(acc[nt][0], a10, fmaf(acc[nt][1], a11, s1r0));
        s2r0 = fmaf(acc[nt][0], a20, fmaf(acc[nt][1], a21, s2r0));
        s1r1 = fmaf(acc[nt][2], a10, fmaf(acc[nt][3], a11, s1r1));
        s2r1 = fmaf(acc[nt][2], a20, fmaf(acc[nt][3], a21, s2r1));
        tr[(d0 + 0) * 64 + r0] = __float2half_rn(acc[nt][0]);
        tr[(d0 + 1) * 64 + r0] = __float2half_rn(acc[nt][1]);
        tr[(d0 + 0) * 64 + r1] = __float2half_rn(acc[nt][2]);
        tr[(d0 + 1) * 64 + r1] = __float2half_rn(acc[nt][3]);
    }
    #pragma unroll
    for (int off = 1; off <= 2; off <<= 1) {
        s1r0 += __shfl_xor_sync(0xffffffffu, s1r0, off);
        s2r0 += __shfl_xor_sync(0xffffffffu, s2r0, off);
        s1r1 += __shfl_xor_sync(0xffffffffu, s1r1, off);
        s2r1 += __shfl_xor_sync(0xffffffffu, s2r1, off);
    }
    if ((lid & 3) == 0) {
        ps1[nh * 64 + r0] = s1r0; ps2[nh * 64 + r0] = s2r0;
        ps1[nh * 64 + r1] = s1r1; ps2[nh * 64 + r1] = s2r1;
    }
    __syncthreads();

    if (tid < 64) {
        const float s1 = ps1[tid] + ps1[64 + tid];
        const float s2 = ps2[tid] + ps2[64 + tid];
        g_s1[gi0 + tid] = s1;
        g_s2[gi0 + tid] = s2;
        float m = s2;
        #pragma unroll
        for (int off = 16; off; off >>= 1) m = fmaxf(m, __shfl_down_sync(0xffffffffu, m, off));
        if ((tid & 31) == 0) atomicMax(&g_s2max_u[b], fkey(m));
    }

    #pragma unroll
    for (int c = 0; c < 2; c++) {
        const int idx = tid + 256 * c;
        const int d = idx >> 3;
        const int c8 = idx & 7;
        const uint4 val = *reinterpret_cast<const uint4*>(tr + d * 64 + c8 * 8);
        *reinterpret_cast<uint4*>(g_WhT + ((size_t)(b * DOUT + d)) * NN + rowb + c8 * 8) = val;
    }
}

// ============================================================
// Kernel B: fp16 HMMA GAT main with cp.async distance-2 adj pipeline.
// 256 CTAs x 64 rows, 8 warps, 2 CTAs/SM.
// iter jt: stage adj(jt+2) [cp.async] + W(jt+1) [regs] -> MMA(jt)
//          -> wait adj(jt+1) -> build P(jt+1) -> bar.
// ============================================================
#define GOFF_PHI(s) ((s) * 8192)
#define GOFF_WHI(s) (16384 + (s) * 8192)
#define GOFF_ADJ(s) (32768 + (s) * 16384)
#define GOFF_U   65536
#define GOFF_V   73728
#define GOFF_AS  81920
#define GOFF_BS  82176
#define GOFF_ZF  82432
#define GAT_SMEM 82688

__global__ __launch_bounds__(256, 2) void gat_main(const int* __restrict__ adj,
                                                   float* __restrict__ out) {
    extern __shared__ char sm[];
    const uint32_t smb = smem_u32(sm);
    const int tid = threadIdx.x;
    const int wid = tid >> 5, lid = tid & 31;
    const int gi0 = blockIdx.x * 64;
    const int b = gi0 >> 11;

    float* u_sh = reinterpret_cast<float*>(sm + GOFF_U);
    float* v_sh = reinterpret_cast<float*>(sm + GOFF_V);
    float* As = reinterpret_cast<float*>(sm + GOFF_AS);
    float* Bs = reinterpret_cast<float*>(sm + GOFF_BS);
    float* zf = reinterpret_cast<float*>(sm + GOFF_ZF);

    // ---- prologue ----
    const float s2m = funkey(g_s2max_u[b]);
    for (int j = tid; j < NN; j += 256) {
        const float s2 = g_s2[b * NN + j];
        u_sh[j] = __expf(s2);
        v_sh[j] = __expf(ALPHA * s2);
    }
    if (tid < 64) {
        const float s1 = g_s1[gi0 + tid];
        const float t = s1 + s2m;
        const float m = (t > 0.f) ? t : ALPHA * t;
        As[tid] = 0.5f * __expf(s1 - m);
        Bs[tid] = 0.5f * __expf(ALPHA * s1 - m);
    }
    __syncthreads();

    // ---- geometry ----
    const int r16 = tid >> 4;
    const int chunk = tid & 15;
    const int chunk4 = chunk * 4;

    float Ar[4], Br[4];
    #pragma unroll
    for (int i = 0; i < 4; i++) { Ar[i] = As[r16 + 16 * i]; Br[i] = Bs[r16 + 16 * i]; }

    float acc[4][4];
    #pragma unroll
    for (int n = 0; n < 4; n++)
        #pragma unroll
        for (int k = 0; k < 4; k++) acc[n][k] = 0.f;
    float zacc[4] = {0.f, 0.f, 0.f, 0.f};

    const int mq = wid & 3, nh = wid >> 2;
    const int rr = lid & 7, q = lid >> 3, qh = q >> 1, ql = q & 1;
    const int rowA = mq * 16 + rr + (ql << 3);
    const uint32_t baseA = (uint32_t)(rowA * 128);
    const int xA = rowA & 7;
    const int rbB = nh * 32 + (qh << 3) + rr;

    const int wdrow = tid >> 3, wun = tid & 7;
    const uint32_t wdst0 = (uint32_t)(wdrow * 128 + ((wun ^ (wdrow & 7)) << 4));
    const uint32_t wdst1 = (uint32_t)((wdrow + 32) * 128 + ((wun ^ ((wdrow + 32) & 7)) << 4));
    const __half* wsrc = g_WhT + ((size_t)(b * DOUT + wdrow)) * NN + wun * 8;
    const int* asrc = adj + (size_t)(gi0 + r16) * NN + chunk4;

    // per-thread adj staging addresses (self-staged, self-consumed)
    const uint32_t adst = (uint32_t)(r16 * 256 + chunk * 16);   // + i*4096 + GOFF_ADJ(s)

    // ---- prologue staging: adj tiles 0 and 1 via cp.async ----
    #pragma unroll
    for (int i = 0; i < 4; i++)
        CP_ASYNC16(smb + GOFF_ADJ(0) + adst + i * 4096, asrc + (size_t)(16 * i) * NN);
    CP_COMMIT();
    #pragma unroll
    for (int i = 0; i < 4; i++)
        CP_ASYNC16(smb + GOFF_ADJ(1) + adst + i * 4096, asrc + (size_t)(16 * i) * NN + 64);
    CP_COMMIT();

    uint4 pwh0 = *reinterpret_cast<const uint4*>(wsrc);
    uint4 pwh1 = *reinterpret_cast<const uint4*>(wsrc + (size_t)32 * NN);

    CP_WAIT1();    // adj tile 0 landed (tile 1 may be in flight)

    // build stage 0
    {
        *reinterpret_cast<uint4*>(sm + GOFF_WHI(0) + wdst0) = pwh0;
        *reinterpret_cast<uint4*>(sm + GOFF_WHI(0) + wdst1) = pwh1;
        const float4 uu = *reinterpret_cast<const float4*>(u_sh + chunk4);
        const float4 vv = *reinterpret_cast<const float4*>(v_sh + chunk4);
        #pragma unroll
        for (int i = 0; i < 4; i++) {
            const int row = r16 + 16 * i;
            const int4 av = *reinterpret_cast<const int4*>(sm + GOFF_ADJ(0) + adst + i * 4096);
            float4 p;
            p.x = fmaxf(Ar[i] * uu.x, Br[i] * vv.x) * __int_as_float(av.x << 30);
            p.y = fmaxf(Ar[i] * uu.y, Br[i] * vv.y) * __int_as_float(av.y << 30);
            p.z = fmaxf(Ar[i] * uu.z, Br[i] * vv.z) * __int_as_float(av.z << 30);
            p.w = fmaxf(Ar[i] * uu.w, Br[i] * vv.w) * __int_as_float(av.w << 30);
            zacc[i] += (p.x + p.y) + (p.z + p.w);
            const uint32_t h0 = pkhf2(p.x, p.y);
            const uint32_t h1 = pkhf2(p.z, p.w);
            const uint32_t swo = (uint32_t)(row * 128 + (((chunk >> 1) ^ (row & 7)) << 4) +
                                            ((chunk & 1) << 3));
            *reinterpret_cast<uint2*>(sm + GOFF_PHI(0) + swo) = make_uint2(h0, h1);
        }
    }
    __syncthreads();

    for (int jt = 0; jt < 32; jt++) {
        const int cur = jt & 1;
        const bool more = (jt < 31);
        const int jn = (jt + 1) * 64;

        // ---- stage adj(jt+2) into slot cur (its previous tile was consumed last iter) ----
        if (jt < 30) {
            const int j2 = (jt + 2) * 64;
            #pragma unroll
            for (int i = 0; i < 4; i++)
                CP_ASYNC16(smb + GOFF_ADJ(cur) + adst + i * 4096,
                           asrc + (size_t)(16 * i) * NN + j2);
            CP_COMMIT();
        } else {
            CP_COMMIT();   // empty group keeps wait_group accounting uniform
        }
        // ---- W(jt+1) register prefetch (L2-resident) ----
        if (more) {
            pwh0 = *reinterpret_cast<const uint4*>(wsrc + jn);
            pwh1 = *reinterpret_cast<const uint4*>(wsrc + (size_t)32 * NN + jn);
        }

        // ---- MMA on current stage ----
        {
            const uint32_t oPhi = GOFF_PHI(cur), oWhi = GOFF_WHI(cur);
            #pragma unroll
            for (int t = 0; t < 4; t++) {
                uint32_t Ah[4];
                const uint32_t ua = baseA + (uint32_t)(((2 * t + qh) ^ xA) << 4);
                ldsm4(Ah, smb + oPhi + ua);
                #pragma unroll
                for (int ntp = 0; ntp < 2; ntp++) {
                    const int rowB = rbB + ntp * 16;
                    const uint32_t ab = (uint32_t)(rowB * 128 +
                                                   (((2 * t + ql) ^ (rowB & 7)) << 4));
                    uint32_t Bh[4];
                    ldsm4(Bh, smb + oWhi + ab);
                    mma_f16(acc[2 * ntp],     Ah, Bh[0], Bh[1]);
                    mma_f16(acc[2 * ntp + 1], Ah, Bh[2], Bh[3]);
                }
            }
        }

        // ---- build next stage (adj(jt+1) guaranteed by wait_group 1) ----
        if (more) {
            const int nxt = cur ^ 1;
            CP_WAIT1();
            *reinterpret_cast<uint4*>(sm + GOFF_WHI(nxt) + wdst0) = pwh0;
            *reinterpret_cast<uint4*>(sm + GOFF_WHI(nxt) + wdst1) = pwh1;
            const float4 uu = *reinterpret_cast<const float4*>(u_sh + jn + chunk4);
            const float4 vv = *reinterpret_cast<const float4*>(v_sh + jn + chunk4);
            #pragma unroll
            for (int i = 0; i < 4; i++) {
                const int row = r16 + 16 * i;
                const int4 av = *reinterpret_cast<const int4*>(sm + GOFF_ADJ(nxt) + adst + i * 4096);
                float4 p;
                p.x = fmaxf(Ar[i] * uu.x, Br[i] * vv.x) * __int_as_float(av.x << 30);
                p.y = fmaxf(Ar[i] * uu.y, Br[i] * vv.y) * __int_as_float(av.y << 30);
                p.z = fmaxf(Ar[i] * uu.z, Br[i] * vv.z) * __int_as_float(av.z << 30);
                p.w = fmaxf(Ar[i] * uu.w, Br[i] * vv.w) * __int_as_float(av.w << 30);
                zacc[i] += (p.x + p.y) + (p.z + p.w);
                const uint32_t h0 = pkhf2(p.x, p.y);
                const uint32_t h1 = pkhf2(p.z, p.w);
                const uint32_t swo = (uint32_t)(row * 128 + (((chunk >> 1) ^ (row & 7)) << 4) +
                                                ((chunk & 1) << 3));
                *reinterpret_cast<uint2*>(sm + GOFF_PHI(nxt) + swo) = make_uint2(h0, h1);
            }
        }
        __syncthreads();
    }

    // ---- Z reduction (alias P_HI(0)) ----
    float* zp = reinterpret_cast<float*>(sm + GOFF_PHI(0));
    #pragma unroll
    for (int i = 0; i < 4; i++) zp[i * 256 + tid] = zacc[i];
    __syncthreads();
    if (tid < 64) {
        const float* src = zp + (tid >> 4) * 256 + (tid & 15) * 16;
        float z = 0.f;
        #pragma unroll
        for (int t = 0; t < 16; t++) z += src[t];
        zf[tid] = z;
    }
    __syncthreads();

    // ---- normalize + store ----
    const int r0 = mq * 16 + (lid >> 2), r1 = r0 + 8;
    const float inv0 = 1.f / zf[r0];
    const float inv1 = 1.f / zf[r1];
    float* o0 = out + (size_t)(gi0 + r0) * DOUT + nh * 32 + (lid & 3) * 2;
    float* o1 = out + (size_t)(gi0 + r1) * DOUT + nh * 32 + (lid & 3) * 2;
    #pragma unroll
    for (int nt = 0; nt < 4; nt++) {
        *reinterpret_cast<float2*>(o0 + nt * 8) = make_float2(acc[nt][0] * inv0, acc[nt][1] * inv0);
        *reinterpret_cast<float2*>(o1 + nt * 8) = make_float2(acc[nt][2] * inv1, acc[nt][3] * inv1);
    }
}

// ============================================================
extern "C" void kernel_launch(void* const* d_in, const int* in_sizes, int n_in,
                              void* d_out, int out_size) {
    const float* h   = (const float*)d_in[0];
    const int*   adj = (const int*)d_in[1];
    const float* W   = (const float*)d_in[2];
    const float* a   = (const float*)d_in[3];
    float* out = (float*)d_out;

    cudaFuncSetAttribute(gat_main, cudaFuncAttributeMaxDynamicSharedMemorySize, GAT_SMEM);
    cudaFuncSetAttribute(wh_kernel, cudaFuncAttributeMaxDynamicSharedMemorySize, WH_SMEM);

    wh_kernel<<<(BATCH * NN) / 64, 256, WH_SMEM>>>(h, W, a);
    gat_main<<<(BATCH * NN) / 64, 256, GAT_SMEM>>>(adj, out);
}

// round 9
// speedup vs baseline: 1.0660x; 1.0660x over previous
#include <cuda_runtime.h>
#include <cuda_bf16.h>
#include <cuda_fp16.h>
#include <cstdint>

#define BATCH 8
#define NN    2048
#define KDIM  256
#define DOUT  64
#define ALPHA 0.2f

// ---------------- scratch ----------------
__device__ __half g_WhT[BATCH * DOUT * NN];   // [b][d][j] fp16, 2MB
__device__ float g_s1[BATCH * NN];
__device__ float g_s2[BATCH * NN];
__device__ float g_u[BATCH * NN];             // exp(s2)
__device__ float g_v[BATCH * NN];             // exp(alpha*s2)
__device__ unsigned int g_s2max_u[BATCH];     // order-preserving float keys

// ---------------- helpers ----------------
__device__ __forceinline__ uint32_t smem_u32(const void* p) {
    uint32_t a;
    asm("{ .reg .u64 t; cvta.to.shared.u64 t, %1; cvt.u32.u64 %0, t; }" : "=r"(a) : "l"(p));
    return a;
}
__device__ __forceinline__ void ldsm4(uint32_t (&r)[4], uint32_t addr) {
    asm volatile("ldmatrix.sync.aligned.m8n8.x4.shared.b16 {%0,%1,%2,%3}, [%4];"
                 : "=r"(r[0]), "=r"(r[1]), "=r"(r[2]), "=r"(r[3]) : "r"(addr));
}
__device__ __forceinline__ void mma_bf16(float (&d)[4], const uint32_t (&a)[4],
                                         uint32_t b0, uint32_t b1) {
    asm volatile("mma.sync.aligned.m16n8k16.row.col.f32.bf16.bf16.f32 "
                 "{%0,%1,%2,%3}, {%4,%5,%6,%7}, {%8,%9}, {%0,%1,%2,%3};"
                 : "+f"(d[0]), "+f"(d[1]), "+f"(d[2]), "+f"(d[3])
                 : "r"(a[0]), "r"(a[1]), "r"(a[2]), "r"(a[3]), "r"(b0), "r"(b1));
}
__device__ __forceinline__ void mma_f16(float (&d)[4], const uint32_t (&a)[4],
                                        uint32_t b0, uint32_t b1) {
    asm volatile("mma.sync.aligned.m16n8k16.row.col.f32.f16.f16.f32 "
                 "{%0,%1,%2,%3}, {%4,%5,%6,%7}, {%8,%9}, {%0,%1,%2,%3};"
                 : "+f"(d[0]), "+f"(d[1]), "+f"(d[2]), "+f"(d[3])
                 : "r"(a[0]), "r"(a[1]), "r"(a[2]), "r"(a[3]), "r"(b0), "r"(b1));
}
__device__ __forceinline__ uint32_t pkbf2(float x, float y) {
    __nv_bfloat162 t = __floats2bfloat162_rn(x, y);
    return *reinterpret_cast<uint32_t*>(&t);
}
__device__ __forceinline__ uint32_t hibits2(float x, float y) {
    return __byte_perm(__float_as_uint(x), __float_as_uint(y), 0x7632);
}
__device__ __forceinline__ float resid(float x) {
    return x - __uint_as_float(__float_as_uint(x) & 0xFFFF0000u);
}
__device__ __forceinline__ uint32_t pkhf2(float x, float y) {
    __half2 t = __floats2half2_rn(x, y);
    return *reinterpret_cast<uint32_t*>(&t);
}
__device__ __forceinline__ uint32_t fkey(float f) {
    const uint32_t b = __float_as_uint(f);
    return b ^ ((uint32_t)((int)b >> 31) | 0x80000000u);
}
__device__ __forceinline__ float funkey(uint32_t k) {
    const uint32_t b = (k & 0x80000000u) ? (k ^ 0x80000000u) : ~k;
    return __uint_as_float(b);
}

// ============================================================
// Kernel A (HMMA): Wh = h @ W. 256 CTAs x 64 rows, 8 warps, 2 CTAs/SM.
// Emits s1, s2, u=exp(s2), v=exp(a*s2), s2max key, WhT fp16.
// ============================================================
#define WOFF_HH 0
#define WOFF_HL 8192
#define WOFF_WH 16384
#define WOFF_WL 24576
#define WOFF_TR 0
#define WOFF_PS 32768
#define WH_SMEM 33792

__global__ __launch_bounds__(256, 2) void wh_kernel(const float* __restrict__ h,
                                                    const float* __restrict__ W,
                                                    const float* __restrict__ a) {
    extern __shared__ char sw[];
    const uint32_t smb = smem_u32(sw);
    const int tid = threadIdx.x;
    const int wid = tid >> 5, lid = tid & 31;
    const int gi0 = blockIdx.x * 64;
    const int b = gi0 >> 11;
    const int rowb = gi0 & 2047;

    float acc[4][4];
    #pragma unroll
    for (int n = 0; n < 4; n++)
        #pragma unroll
        for (int k = 0; k < 4; k++) acc[n][k] = 0.f;

    const int mq = wid & 3, nh = wid >> 2;
    const int rr = lid & 7, q = lid >> 3, qh = q >> 1, ql = q & 1;
    const int rowA = mq * 16 + rr + (ql << 3);
    const uint32_t baseA = (uint32_t)(rowA * 128);
    const int xA = rowA & 7;
    const int rbB = nh * 32 + (qh << 3) + rr;

    const int hrow = tid >> 2, hq = tid & 3;
    const float* hsrc = h + (size_t)(gi0 + hrow) * KDIM + hq * 16;
    const int wdd = tid >> 2, wkg = tid & 3;

    for (int kt = 0; kt < 4; kt++) {
        __syncthreads();
        #pragma unroll
        for (int g = 0; g < 2; g++) {
            const float4 f0 = *reinterpret_cast<const float4*>(hsrc + kt * 64 + g * 8);
            const float4 f1 = *reinterpret_cast<const float4*>(hsrc + kt * 64 + g * 8 + 4);
            uint4 hi4, lo4;
            hi4.x = hibits2(f0.x, f0.y); hi4.y = hibits2(f0.z, f0.w);
            hi4.z = hibits2(f1.x, f1.y); hi4.w = hibits2(f1.z, f1.w);
            lo4.x = pkbf2(resid(f0.x), resid(f0.y));
            lo4.y = pkbf2(resid(f0.z), resid(f0.w));
            lo4.z = pkbf2(resid(f1.x), resid(f1.y));
            lo4.w = pkbf2(resid(f1.z), resid(f1.w));
            const int gran = hq * 2 + g;
            const uint32_t addr = (uint32_t)(hrow * 128 + ((gran ^ (hrow & 7)) << 4));
            *reinterpret_cast<uint4*>(sw + WOFF_HH + addr) = hi4;
            *reinterpret_cast<uint4*>(sw + WOFF_HL + addr) = lo4;
        }
        {
            uint32_t hi[8], lo[8];
            #pragma unroll
            for (int t = 0; t < 8; t++) {
                const float x0 = W[(kt * 64 + wkg * 16 + 2 * t) * DOUT + wdd];
                const float x1 = W[(kt * 64 + wkg * 16 + 2 * t + 1) * DOUT + wdd];
                hi[t] = hibits2(x0, x1);
                lo[t] = pkbf2(resid(x0), resid(x1));
            }
            const uint32_t a0 = (uint32_t)(wdd * 128 + (((wkg * 2) ^ (wdd & 7)) << 4));
            const uint32_t a1 = (uint32_t)(wdd * 128 + (((wkg * 2 + 1) ^ (wdd & 7)) << 4));
            *reinterpret_cast<uint4*>(sw + WOFF_WH + a0) = make_uint4(hi[0], hi[1], hi[2], hi[3]);
            *reinterpret_cast<uint4*>(sw + WOFF_WH + a1) = make_uint4(hi[4], hi[5], hi[6], hi[7]);
            *reinterpret_cast<uint4*>(sw + WOFF_WL + a0) = make_uint4(lo[0], lo[1], lo[2], lo[3]);
            *reinterpret_cast<uint4*>(sw + WOFF_WL + a1) = make_uint4(lo[4], lo[5], lo[6], lo[7]);
        }
        __syncthreads();
        #pragma unroll
        for (int t = 0; t < 4; t++) {
            uint32_t Ah[4], Al[4];
            const uint32_t ua = baseA + (uint32_t)(((2 * t + qh) ^ xA) << 4);
            ldsm4(Ah, smb + WOFF_HH + ua);
            ldsm4(Al, smb + WOFF_HL + ua);
            #pragma unroll
            for (int ntp = 0; ntp < 2; ntp++) {
                const int rowB = rbB + ntp * 16;
                const uint32_t ab = (uint32_t)(rowB * 128 + (((2 * t + ql) ^ (rowB & 7)) << 4));
                uint32_t Bh[4], Bl[4];
                ldsm4(Bh, smb + WOFF_WH + ab);
                ldsm4(Bl, smb + WOFF_WL + ab);
                mma_bf16(acc[2 * ntp],     Ah, Bh[0], Bh[1]);
                mma_bf16(acc[2 * ntp],     Ah, Bl[0], Bl[1]);
                mma_bf16(acc[2 * ntp],     Al, Bh[0], Bh[1]);
                mma_bf16(acc[2 * ntp + 1], Ah, Bh[2], Bh[3]);
                mma_bf16(acc[2 * ntp + 1], Ah, Bl[2], Bl[3]);
                mma_bf16(acc[2 * ntp + 1], Al, Bh[2], Bh[3]);
            }
        }
    }
    __syncthreads();

    const int r0 = mq * 16 + (lid >> 2), r1 = r0 + 8;
    float s1r0 = 0.f, s2r0 = 0.f, s1r1 = 0.f, s2r1 = 0.f;
    __half* tr = reinterpret_cast<__half*>(sw + WOFF_TR);
    float* ps1 = reinterpret_cast<float*>(sw + WOFF_PS);
    float* ps2 = ps1 + 128;
    #pragma unroll
    for (int nt = 0; nt < 4; nt++) {
        const int d0 = nh * 32 + nt * 8 + (lid & 3) * 2;
        const float a10 = a[d0], a11 = a[d0 + 1];
        const float a20 = a[64 + d0], a21 = a[64 + d0 + 1];
        s1r0 = fmaf(acc[nt][0], a10, fmaf(acc[nt][1], a11, s1r0));
        s2r0 = fmaf(acc[nt][0], a20, fmaf(acc[nt][1], a21, s2r0));
        s1r1 = fmaf(acc[nt][2], a10, fmaf(acc[nt][3], a11, s1r1));
        s2r1 = fmaf(acc[nt][2], a20, fmaf(acc[nt][3], a21, s2r1));
        tr[(d0 + 0) * 64 + r0] = __float2half_rn(acc[nt][0]);
        tr[(d0 + 1) * 64 + r0] = __float2half_rn(acc[nt][1]);
        tr[(d0 + 0) * 64 + r1] = __float2half_rn(acc[nt][2]);
        tr[(d0 + 1) * 64 + r1] = __float2half_rn(acc[nt][3]);
    }
    #pragma unroll
    for (int off = 1; off <= 2; off <<= 1) {
        s1r0 += __shfl_xor_sync(0xffffffffu, s1r0, off);
        s2r0 += __shfl_xor_sync(0xffffffffu, s2r0, off);
        s1r1 += __shfl_xor_sync(0xffffffffu, s1r1, off);
        s2r1 += __shfl_xor_sync(0xffffffffu, s2r1, off);
    }
    if ((lid & 3) == 0) {
        ps1[nh * 64 + r0] = s1r0; ps2[nh * 64 + r0] = s2r0;
        ps1[nh * 64 + r1] = s1r1; ps2[nh * 64 + r1] = s2r1;
    }
    __syncthreads();

    if (tid < 64) {
        const float s1 = ps1[tid] + ps1[64 + tid];
        const float s2 = ps2[tid] + ps2[64 + tid];
        g_s1[gi0 + tid] = s1;
        g_s2[gi0 + tid] = s2;
        g_u[gi0 + tid] = __expf(s2);
        g_v[gi0 + tid] = __expf(ALPHA * s2);
        float m = s2;
        #pragma unroll
        for (int off = 16; off; off >>= 1) m = fmaxf(m, __shfl_down_sync(0xffffffffu, m, off));
        if ((tid & 31) == 0) atomicMax(&g_s2max_u[b], fkey(m));
    }

    #pragma unroll
    for (int c = 0; c < 2; c++) {
        const int idx = tid + 256 * c;
        const int d = idx >> 3;
        const int c8 = idx & 7;
        const uint4 val = *reinterpret_cast<const uint4*>(tr + d * 64 + c8 * 8);
        *reinterpret_cast<uint4*>(g_WhT + ((size_t)(b * DOUT + d)) * NN + rowb + c8 * 8) = val;
    }
}

// ============================================================
// Kernel B: fp16 HMMA GAT main. 256 CTAs x 64 rows, 8 warps, 3 CTAs/SM.
// Register adj prefetch (distance 1), u/v loaded (not computed) in prologue.
// ============================================================
#define GOFF_PHI(s) ((s) * 8192)
#define GOFF_WHI(s) (16384 + (s) * 8192)
#define GOFF_U   32768
#define GOFF_V   40960
#define GOFF_AS  49152
#define GOFF_BS  49408
#define GOFF_ZF  49664
#define GAT_SMEM 49920

__global__ __launch_bounds__(256, 3) void gat_main(const int* __restrict__ adj,
                                                   float* __restrict__ out) {
    extern __shared__ char sm[];
    const uint32_t smb = smem_u32(sm);
    const int tid = threadIdx.x;
    const int wid = tid >> 5, lid = tid & 31;
    const int gi0 = blockIdx.x * 64;
    const int b = gi0 >> 11;

    float* u_sh = reinterpret_cast<float*>(sm + GOFF_U);
    float* v_sh = reinterpret_cast<float*>(sm + GOFF_V);
    float* As = reinterpret_cast<float*>(sm + GOFF_AS);
    float* Bs = reinterpret_cast<float*>(sm + GOFF_BS);
    float* zf = reinterpret_cast<float*>(sm + GOFF_ZF);

    // ---- prologue: copy precomputed u/v; compute A/B (64 exps) ----
    {
        const float4* us = reinterpret_cast<const float4*>(g_u + b * NN);
        const float4* vs = reinterpret_cast<const float4*>(g_v + b * NN);
        float4* ud = reinterpret_cast<float4*>(u_sh);
        float4* vd = reinterpret_cast<float4*>(v_sh);
        #pragma unroll
        for (int c = 0; c < 2; c++) {
            ud[tid + 256 * c] = us[tid + 256 * c];
            vd[tid + 256 * c] = vs[tid + 256 * c];
        }
    }
    if (tid < 64) {
        const float s2m = funkey(g_s2max_u[b]);
        const float s1 = g_s1[gi0 + tid];
        const float t = s1 + s2m;
        const float m = (t > 0.f) ? t : ALPHA * t;
        As[tid] = 0.5f * __expf(s1 - m);
        Bs[tid] = 0.5f * __expf(ALPHA * s1 - m);
    }
    __syncthreads();

    // ---- geometry ----
    const int r16 = tid >> 4;
    const int chunk = tid & 15;
    const int chunk4 = chunk * 4;

    float Ar[4], Br[4];
    #pragma unroll
    for (int i = 0; i < 4; i++) { Ar[i] = As[r16 + 16 * i]; Br[i] = Bs[r16 + 16 * i]; }

    float acc[4][4];
    #pragma unroll
    for (int n = 0; n < 4; n++)
        #pragma unroll
        for (int k = 0; k < 4; k++) acc[n][k] = 0.f;
    float zacc[4] = {0.f, 0.f, 0.f, 0.f};

    const int mq = wid & 3, nh = wid >> 2;
    const int rr = lid & 7, q = lid >> 3, qh = q >> 1, ql = q & 1;
    const int rowA = mq * 16 + rr + (ql << 3);
    const uint32_t baseA = (uint32_t)(rowA * 128);
    const int xA = rowA & 7;
    const int rbB = nh * 32 + (qh << 3) + rr;

    const int wdrow = tid >> 3, wun = tid & 7;
    const uint32_t wdst0 = (uint32_t)(wdrow * 128 + ((wun ^ (wdrow & 7)) << 4));
    const uint32_t wdst1 = (uint32_t)((wdrow + 32) * 128 + ((wun ^ ((wdrow + 32) & 7)) << 4));
    const __half* wsrc = g_WhT + ((size_t)(b * DOUT + wdrow)) * NN + wun * 8;
    const int* asrc = adj + (size_t)(gi0 + r16) * NN + chunk4;

    // ---- prefetch ----
    int4 adjr[4];
    uint4 pwh0, pwh1;
    #pragma unroll
    for (int i = 0; i < 4; i++)
        adjr[i] = *reinterpret_cast<const int4*>(asrc + (size_t)(16 * i) * NN);
    pwh0 = *reinterpret_cast<const uint4*>(wsrc);
    pwh1 = *reinterpret_cast<const uint4*>(wsrc + (size_t)32 * NN);

    // build stage 0
    {
        *reinterpret_cast<uint4*>(sm + GOFF_WHI(0) + wdst0) = pwh0;
        *reinterpret_cast<uint4*>(sm + GOFF_WHI(0) + wdst1) = pwh1;
        const float4 uu = *reinterpret_cast<const float4*>(u_sh + chunk4);
        const float4 vv = *reinterpret_cast<const float4*>(v_sh + chunk4);
        #pragma unroll
        for (int i = 0; i < 4; i++) {
            const int row = r16 + 16 * i;
            const int4 av = adjr[i];
            float4 p;
            p.x = fmaxf(Ar[i] * uu.x, Br[i] * vv.x) * __int_as_float(av.x << 30);
            p.y = fmaxf(Ar[i] * uu.y, Br[i] * vv.y) * __int_as_float(av.y << 30);
            p.z = fmaxf(Ar[i] * uu.z, Br[i] * vv.z) * __int_as_float(av.z << 30);
            p.w = fmaxf(Ar[i] * uu.w, Br[i] * vv.w) * __int_as_float(av.w << 30);
            zacc[i] += (p.x + p.y) + (p.z + p.w);
            const uint32_t h0 = pkhf2(p.x, p.y);
            const uint32_t h1 = pkhf2(p.z, p.w);
            const uint32_t swo = (uint32_t)(row * 128 + (((chunk >> 1) ^ (row & 7)) << 4) +
                                            ((chunk & 1) << 3));
            *reinterpret_cast<uint2*>(sm + GOFF_PHI(0) + swo) = make_uint2(h0, h1);
        }
    }
    __syncthreads();

    for (int jt = 0; jt < 32; jt++) {
        const int cur = jt & 1;
        const bool more = (jt < 31);
        const int jn = (jt + 1) * 64;

        if (more) {
            #pragma unroll
            for (int i = 0; i < 4; i++)
                adjr[i] = *reinterpret_cast<const int4*>(asrc + (size_t)(16 * i) * NN + jn);
            pwh0 = *reinterpret_cast<const uint4*>(wsrc + jn);
            pwh1 = *reinterpret_cast<const uint4*>(wsrc + (size_t)32 * NN + jn);
        }

        // ---- MMA on current stage ----
        {
            const uint32_t oPhi = GOFF_PHI(cur), oWhi = GOFF_WHI(cur);
            #pragma unroll
            for (int t = 0; t < 4; t++) {
                uint32_t Ah[4];
                const uint32_t ua = baseA + (uint32_t)(((2 * t + qh) ^ xA) << 4);
                ldsm4(Ah, smb + oPhi + ua);
                #pragma unroll
                for (int ntp = 0; ntp < 2; ntp++) {
                    const int rowB = rbB + ntp * 16;
                    const uint32_t ab = (uint32_t)(rowB * 128 +
                                                   (((2 * t + ql) ^ (rowB & 7)) << 4));
                    uint32_t Bh[4];
                    ldsm4(Bh, smb + oWhi + ab);
                    mma_f16(acc[2 * ntp],     Ah, Bh[0], Bh[1]);
                    mma_f16(acc[2 * ntp + 1], Ah, Bh[2], Bh[3]);
                }
            }
        }

        // ---- build next stage ----
        if (more) {
            const int nxt = cur ^ 1;
            *reinterpret_cast<uint4*>(sm + GOFF_WHI(nxt) + wdst0) = pwh0;
            *reinterpret_cast<uint4*>(sm + GOFF_WHI(nxt) + wdst1) = pwh1;
            const float4 uu = *reinterpret_cast<const float4*>(u_sh + jn + chunk4);
            const float4 vv = *reinterpret_cast<const float4*>(v_sh + jn + chunk4);
            #pragma unroll
            for (int i = 0; i < 4; i++) {
                const int row = r16 + 16 * i;
                const int4 av = adjr[i];
                float4 p;
                p.x = fmaxf(Ar[i] * uu.x, Br[i] * vv.x) * __int_as_float(av.x << 30);
                p.y = fmaxf(Ar[i] * uu.y, Br[i] * vv.y) * __int_as_float(av.y << 30);
                p.z = fmaxf(Ar[i] * uu.z, Br[i] * vv.z) * __int_as_float(av.z << 30);
                p.w = fmaxf(Ar[i] * uu.w, Br[i] * vv.w) * __int_as_float(av.w << 30);
                zacc[i] += (p.x + p.y) + (p.z + p.w);
                const uint32_t h0 = pkhf2(p.x, p.y);
                const uint32_t h1 = pkhf2(p.z, p.w);
                const uint32_t swo = (uint32_t)(row * 128 + (((chunk >> 1) ^ (row & 7)) << 4) +
                                                ((chunk & 1) << 3));
                *reinterpret_cast<uint2*>(sm + GOFF_PHI(nxt) + swo) = make_uint2(h0, h1);
            }
        }
        __syncthreads();
    }

    // ---- Z reduction (alias P_HI(0)) ----
    float* zp = reinterpret_cast<float*>(sm + GOFF_PHI(0));
    #pragma unroll
    for (int i = 0; i < 4; i++) zp[i * 256 + tid] = zacc[i];
    __syncthreads();
    if (tid < 64) {
        const float* src = zp + (tid >> 4) * 256 + (tid & 15) * 16;
        float z = 0.f;
        #pragma unroll
        for (int t = 0; t < 16; t++) z += src[t];
        zf[tid] = z;
    }
    __syncthreads();

    // ---- normalize + store ----
    const int r0 = mq * 16 + (lid >> 2), r1 = r0 + 8;
    const float inv0 = 1.f / zf[r0];
    const float inv1 = 1.f / zf[r1];
    float* o0 = out + (size_t)(gi0 + r0) * DOUT + nh * 32 + (lid & 3) * 2;
    float* o1 = out + (size_t)(gi0 + r1) * DOUT + nh * 32 + (lid & 3) * 2;
    #pragma unroll
    for (int nt = 0; nt < 4; nt++) {
        *reinterpret_cast<float2*>(o0 + nt * 8) = make_float2(acc[nt][0] * inv0, acc[nt][1] * inv0);
        *reinterpret_cast<float2*>(o1 + nt * 8) = make_float2(acc[nt][2] * inv1, acc[nt][3] * inv1);
    }
}

// ============================================================
extern "C" void kernel_launch(void* const* d_in, const int* in_sizes, int n_in,
                              void* d_out, int out_size) {
    const float* h   = (const float*)d_in[0];
    const int*   adj = (const int*)d_in[1];
    const float* W   = (const float*)d_in[2];
    const float* a   = (const float*)d_in[3];
    float* out = (float*)d_out;

    cudaFuncSetAttribute(gat_main, cudaFuncAttributeMaxDynamicSharedMemorySize, GAT_SMEM);
    cudaFuncSetAttribute(wh_kernel, cudaFuncAttributeMaxDynamicSharedMemorySize, WH_SMEM);

    wh_kernel<<<(BATCH * NN) / 64, 256, WH_SMEM>>>(h, W, a);
    gat_main<<<(BATCH * NN) / 64, 256, GAT_SMEM>>>(adj, out);
}